// round 1
// baseline (speedup 1.0000x reference)
#include <cuda_runtime.h>
#include <math.h>

// Problem constants (fixed by the dataset; k_input/k_process inputs are always 2048/1024)
#define BB   8
#define SS   2048
#define DM   1024
#define NIN  4096
#define NP   2048
#define DR   256
#define KI   2048
#define KP   1024

// ---------------- scratch (static __device__ globals; no allocation) ----------------
__device__ float g_gctx [BB * DM];
__device__ float g_h    [BB * 2 * DR];
__device__ float g_hn   [BB * 2 * DR];
__device__ float g_query[BB * DR];
__device__ float g_logits[BB * NIN];
__device__ float g_scores[BB * NP];
__device__ int   g_iidx [BB * KI];
__device__ int   g_pidx [BB * KP];
__device__ float g_selin[(size_t)BB * SS * KI];   // 134 MB
__device__ float g_wsel [(size_t)BB * NP * KI];   // 134 MB
__device__ float g_pa   [(size_t)BB * SS * NP];   // 134 MB
__device__ float g_pasel[(size_t)BB * SS * KP];   //  67 MB

__device__ __forceinline__ float geluf(float v) {
    return 0.5f * v * (1.0f + erff(v * 0.70710678118654752440f));
}

// ---------------- router ----------------

// gctx[b,d] = max_s x[b,s,d]
__global__ void k_rowmax(const float* __restrict__ x) {
    int t = blockIdx.x * blockDim.x + threadIdx.x;   // 8192 threads
    int b = t >> 10, d = t & (DM - 1);
    const float* p = x + (size_t)b * SS * DM + d;
    float m = -INFINITY;
    #pragma unroll 8
    for (int s = 0; s < SS; s++) m = fmaxf(m, p[(size_t)s * DM]);
    g_gctx[t] = m;
}

// h[b,o] = gelu(gctx[b,:] . W1[o,:] + b1[o]),  o < 512
__global__ void k_mlp1(const float* __restrict__ W1, const float* __restrict__ b1) {
    int gw = (blockIdx.x * blockDim.x + threadIdx.x) >> 5;
    int lane = threadIdx.x & 31;
    int b = gw >> 9, o = gw & 511;
    const float* g = g_gctx + b * DM;
    const float* w = W1 + (size_t)o * DM;
    float s = 0.f;
    for (int k = lane; k < DM; k += 32) s += g[k] * w[k];
    #pragma unroll
    for (int off = 16; off; off >>= 1) s += __shfl_xor_sync(0xffffffffu, s, off);
    if (lane == 0) g_h[gw] = geluf(s + b1[o]);
}

// LayerNorm over 512 per batch
__global__ void k_ln(const float* __restrict__ lng, const float* __restrict__ lnb) {
    __shared__ float red[512];
    int b = blockIdx.x, tid = threadIdx.x;
    float v = g_h[b * 512 + tid];
    red[tid] = v;
    for (int s = 256; s; s >>= 1) { __syncthreads(); if (tid < s) red[tid] += red[tid + s]; }
    __syncthreads();
    float mu = red[0] * (1.f / 512.f);
    __syncthreads();
    float dv = v - mu;
    red[tid] = dv * dv;
    for (int s = 256; s; s >>= 1) { __syncthreads(); if (tid < s) red[tid] += red[tid + s]; }
    __syncthreads();
    float var = red[0] * (1.f / 512.f);
    g_hn[b * 512 + tid] = dv * rsqrtf(var + 1e-5f) * lng[tid] + lnb[tid];
}

// query[b,o] = hn[b,:] . W2[o,:] + b2[o]
__global__ void k_mlp2(const float* __restrict__ W2, const float* __restrict__ b2) {
    int gw = (blockIdx.x * blockDim.x + threadIdx.x) >> 5;
    int lane = threadIdx.x & 31;
    int b = gw >> 8, o = gw & 255;
    const float* hrow = g_hn + b * 512;
    const float* w = W2 + (size_t)o * 512;
    float s = 0.f;
    for (int k = lane; k < 512; k += 32) s += hrow[k] * w[k];
    #pragma unroll
    for (int off = 16; off; off >>= 1) s += __shfl_xor_sync(0xffffffffu, s, off);
    if (lane == 0) g_query[gw] = s + b2[o];
}

// logits[b,n] = (query[b,:] . nk[n,:]) / 16
__global__ void k_logits(const float* __restrict__ nk) {
    int gw = (blockIdx.x * blockDim.x + threadIdx.x) >> 5;
    int lane = threadIdx.x & 31;
    int b = gw >> 12, n = gw & (NIN - 1);
    const float* q = g_query + b * DR;
    const float* w = nk + (size_t)n * DR;
    float s = 0.f;
    #pragma unroll
    for (int k = lane; k < DR; k += 32) s += q[k] * w[k];
    #pragma unroll
    for (int off = 16; off; off >>= 1) s += __shfl_xor_sync(0xffffffffu, s, off);
    if (lane == 0) g_logits[gw] = s * 0.0625f;
}

// ---------------- exact top-k via bitonic sort; outputs index set sorted ascending ----------------
__global__ void k_topk(const float* __restrict__ vals, int N, int Ksel, int* __restrict__ outIdx) {
    __shared__ float sv[4096];
    __shared__ int   si[4096];
    int b = blockIdx.x, tid = threadIdx.x, bs = blockDim.x;
    for (int i = tid; i < N; i += bs) { sv[i] = vals[b * N + i]; si[i] = i; }
    // sort by (value desc, index asc)  (matches jax.lax.top_k tie-breaking)
    for (int k = 2; k <= N; k <<= 1) {
        for (int j = k >> 1; j > 0; j >>= 1) {
            __syncthreads();
            for (int i = tid; i < N; i += bs) {
                int l = i ^ j;
                if (l > i) {
                    float vi = sv[i], vl = sv[l];
                    int ii = si[i], il = si[l];
                    bool lFirst = (vl > vi) || (vl == vi && il < ii);
                    bool sw = ((i & k) == 0) ? lFirst : !lFirst;
                    if (sw) { sv[i] = vl; sv[l] = vi; si[i] = il; si[l] = ii; }
                }
            }
        }
    }
    __syncthreads();
    // take top Ksel indices, sort them ascending (set semantics: order irrelevant downstream)
    int* sel = (int*)sv;
    for (int i = tid; i < Ksel; i += bs) sel[i] = si[i];
    for (int k = 2; k <= Ksel; k <<= 1) {
        for (int j = k >> 1; j > 0; j >>= 1) {
            __syncthreads();
            for (int i = tid; i < Ksel; i += bs) {
                int l = i ^ j;
                if (l > i) {
                    int a = sel[i], c = sel[l];
                    bool sw = ((i & k) == 0) ? (c < a) : (c > a);
                    if (sw) { sel[i] = c; sel[l] = a; }
                }
            }
        }
    }
    __syncthreads();
    for (int i = tid; i < Ksel; i += bs) outIdx[b * Ksel + i] = sel[i];
}

// ---------------- gathers / reductions ----------------

// W_sel[b,p,j] = process_weights[p, iidx[b,j]]
__global__ void k_gather_wsel(const float* __restrict__ pw) {
    size_t t = (size_t)blockIdx.x * blockDim.x + threadIdx.x;
    int j = (int)(t & (KI - 1));
    size_t bp = t >> 11;
    int p = (int)(bp & (NP - 1));
    int b = (int)(bp >> 11);
    g_wsel[t] = pw[(size_t)p * NIN + g_iidx[b * KI + j]];
}

// scores[b,p] = mean_s pa[b,s,p]
__global__ void k_scores() {
    int t = blockIdx.x * blockDim.x + threadIdx.x;  // 16384
    int b = t >> 11, p = t & (NP - 1);
    const float* q = g_pa + (size_t)b * SS * NP + p;
    float s = 0.f;
    #pragma unroll 4
    for (int i = 0; i < SS; i++) s += q[(size_t)i * NP];
    g_scores[t] = s * (1.f / (float)SS);
}

// pa_sel[b,s,q] = pa[b,s,pidx[b,q]]
__global__ void k_gather_pasel() {
    size_t t = (size_t)blockIdx.x * blockDim.x + threadIdx.x;
    int q = (int)(t & (KP - 1));
    size_t bs_ = t >> 10;
    int s = (int)(bs_ & (SS - 1));
    int b = (int)(bs_ >> 11);
    g_pasel[t] = g_pa[((size_t)(b * SS + s)) * NP + g_pidx[b * KP + q]];
}

// ---------------- SGEMM: C = act(A * B^T), both row-major K-contiguous, optional row-gather on B ----------------
// 128x128 tile, BK=8, 256 threads, 8x8 microtile split as (4+4 rows)x(4+4 cols)
template<bool DOGELU, bool GATHERB>
__global__ void __launch_bounds__(256, 2) sgemm_nt(
    const float* __restrict__ A, const float* __restrict__ Bm, float* __restrict__ Cm,
    const int* __restrict__ gidx,
    int M, int N, int K, size_t sA, size_t sB, size_t sC, int sG)
{
    int zb = blockIdx.z;
    A  += (size_t)zb * sA;
    Bm += (size_t)zb * sB;
    Cm += (size_t)zb * sC;
    if (GATHERB) gidx += (size_t)zb * sG;
    int m0 = blockIdx.y * 128, n0 = blockIdx.x * 128;

    __shared__ float As[8][128];
    __shared__ float Bs[8][128];

    int tid = threadIdx.x;
    int tx = tid & 15, ty = tid >> 4;

    int a_r = tid >> 1, c4 = (tid & 1) * 4;
    const float* Aptr = A + (size_t)(m0 + a_r) * K + c4;
    int brow = n0 + a_r;
    int bsrc = GATHERB ? gidx[brow] : brow;
    const float* Bptr = Bm + (size_t)bsrc * K + c4;

    float acc[8][8];
    #pragma unroll
    for (int i = 0; i < 8; i++)
        #pragma unroll
        for (int j = 0; j < 8; j++) acc[i][j] = 0.f;

    for (int k0 = 0; k0 < K; k0 += 8) {
        float4 av = *(const float4*)(Aptr + k0);
        float4 bv = *(const float4*)(Bptr + k0);
        __syncthreads();
        As[c4 + 0][a_r] = av.x; As[c4 + 1][a_r] = av.y; As[c4 + 2][a_r] = av.z; As[c4 + 3][a_r] = av.w;
        Bs[c4 + 0][a_r] = bv.x; Bs[c4 + 1][a_r] = bv.y; Bs[c4 + 2][a_r] = bv.z; Bs[c4 + 3][a_r] = bv.w;
        __syncthreads();
        #pragma unroll
        for (int kk = 0; kk < 8; kk++) {
            float4 t0 = *(const float4*)&As[kk][ty * 4];
            float4 t1 = *(const float4*)&As[kk][64 + ty * 4];
            float4 u0 = *(const float4*)&Bs[kk][tx * 4];
            float4 u1 = *(const float4*)&Bs[kk][64 + tx * 4];
            float a[8], b[8];
            a[0]=t0.x; a[1]=t0.y; a[2]=t0.z; a[3]=t0.w; a[4]=t1.x; a[5]=t1.y; a[6]=t1.z; a[7]=t1.w;
            b[0]=u0.x; b[1]=u0.y; b[2]=u0.z; b[3]=u0.w; b[4]=u1.x; b[5]=u1.y; b[6]=u1.z; b[7]=u1.w;
            #pragma unroll
            for (int i = 0; i < 8; i++)
                #pragma unroll
                for (int j = 0; j < 8; j++)
                    acc[i][j] += a[i] * b[j];
        }
    }

    #pragma unroll
    for (int i = 0; i < 8; i++) {
        int row = m0 + ((i < 4) ? (ty * 4 + i) : (64 + ty * 4 + i - 4));
        float4 v0, v1;
        v0.x = acc[i][0]; v0.y = acc[i][1]; v0.z = acc[i][2]; v0.w = acc[i][3];
        v1.x = acc[i][4]; v1.y = acc[i][5]; v1.z = acc[i][6]; v1.w = acc[i][7];
        if (DOGELU) {
            v0.x = geluf(v0.x); v0.y = geluf(v0.y); v0.z = geluf(v0.z); v0.w = geluf(v0.w);
            v1.x = geluf(v1.x); v1.y = geluf(v1.y); v1.z = geluf(v1.z); v1.w = geluf(v1.w);
        }
        *(float4*)(Cm + (size_t)row * N + n0 + tx * 4) = v0;
        *(float4*)(Cm + (size_t)row * N + n0 + 64 + tx * 4) = v1;
    }
}

// ---------------- SGEMM: C = A * B, B row-major N-contiguous with per-batch row gather ----------------
__global__ void __launch_bounds__(256, 2) sgemm_nn_g(
    const float* __restrict__ A, const float* __restrict__ Bm, float* __restrict__ Cm,
    const int* __restrict__ gidx,
    int M, int N, int K, size_t sA, size_t sC, int sG)
{
    int zb = blockIdx.z;
    A  += (size_t)zb * sA;
    Cm += (size_t)zb * sC;
    gidx += (size_t)zb * sG;
    int m0 = blockIdx.y * 128, n0 = blockIdx.x * 128;

    __shared__ float As[8][128];
    __shared__ float Bs[8][128];

    int tid = threadIdx.x;
    int tx = tid & 15, ty = tid >> 4;

    int a_r = tid >> 1, a_c4 = (tid & 1) * 4;
    const float* Aptr = A + (size_t)(m0 + a_r) * K + a_c4;
    int b_k = tid >> 5, b_n4 = (tid & 31) * 4;

    float acc[8][8];
    #pragma unroll
    for (int i = 0; i < 8; i++)
        #pragma unroll
        for (int j = 0; j < 8; j++) acc[i][j] = 0.f;

    for (int k0 = 0; k0 < K; k0 += 8) {
        float4 av = *(const float4*)(Aptr + k0);
        int ridx = gidx[k0 + b_k];
        float4 bv = *(const float4*)(Bm + (size_t)ridx * N + n0 + b_n4);
        __syncthreads();
        As[a_c4 + 0][a_r] = av.x; As[a_c4 + 1][a_r] = av.y; As[a_c4 + 2][a_r] = av.z; As[a_c4 + 3][a_r] = av.w;
        *(float4*)&Bs[b_k][b_n4] = bv;
        __syncthreads();
        #pragma unroll
        for (int kk = 0; kk < 8; kk++) {
            float4 t0 = *(const float4*)&As[kk][ty * 4];
            float4 t1 = *(const float4*)&As[kk][64 + ty * 4];
            float4 u0 = *(const float4*)&Bs[kk][tx * 4];
            float4 u1 = *(const float4*)&Bs[kk][64 + tx * 4];
            float a[8], b[8];
            a[0]=t0.x; a[1]=t0.y; a[2]=t0.z; a[3]=t0.w; a[4]=t1.x; a[5]=t1.y; a[6]=t1.z; a[7]=t1.w;
            b[0]=u0.x; b[1]=u0.y; b[2]=u0.z; b[3]=u0.w; b[4]=u1.x; b[5]=u1.y; b[6]=u1.z; b[7]=u1.w;
            #pragma unroll
            for (int i = 0; i < 8; i++)
                #pragma unroll
                for (int j = 0; j < 8; j++)
                    acc[i][j] += a[i] * b[j];
        }
    }

    #pragma unroll
    for (int i = 0; i < 8; i++) {
        int row = m0 + ((i < 4) ? (ty * 4 + i) : (64 + ty * 4 + i - 4));
        float4 v0, v1;
        v0.x = acc[i][0]; v0.y = acc[i][1]; v0.z = acc[i][2]; v0.w = acc[i][3];
        v1.x = acc[i][4]; v1.y = acc[i][5]; v1.z = acc[i][6]; v1.w = acc[i][7];
        *(float4*)(Cm + (size_t)row * N + n0 + tx * 4) = v0;
        *(float4*)(Cm + (size_t)row * N + n0 + 64 + tx * 4) = v1;
    }
}

// ---------------- launch ----------------
extern "C" void kernel_launch(void* const* d_in, const int* in_sizes, int n_in,
                              void* d_out, int out_size) {
    const float* x   = (const float*)d_in[0];
    // d_in[1] = k_input (2048), d_in[2] = k_process (1024): fixed, hardcoded
    const float* W1  = (const float*)d_in[3];
    const float* b1  = (const float*)d_in[4];
    const float* lng = (const float*)d_in[5];
    const float* lnb = (const float*)d_in[6];
    const float* W2  = (const float*)d_in[7];
    const float* b2  = (const float*)d_in[8];
    const float* nk  = (const float*)d_in[9];
    const float* ip  = (const float*)d_in[10];
    const float* pw  = (const float*)d_in[11];
    const float* po  = (const float*)d_in[12];
    float* out = (float*)d_out;

    float *p_logits, *p_scores, *p_selin, *p_wsel, *p_pa, *p_pasel;
    int *p_iidx, *p_pidx;
    cudaGetSymbolAddress((void**)&p_logits, g_logits);
    cudaGetSymbolAddress((void**)&p_scores, g_scores);
    cudaGetSymbolAddress((void**)&p_selin,  g_selin);
    cudaGetSymbolAddress((void**)&p_wsel,   g_wsel);
    cudaGetSymbolAddress((void**)&p_pa,     g_pa);
    cudaGetSymbolAddress((void**)&p_pasel,  g_pasel);
    cudaGetSymbolAddress((void**)&p_iidx,   g_iidx);
    cudaGetSymbolAddress((void**)&p_pidx,   g_pidx);

    // router
    k_rowmax<<<BB * DM / 256, 256>>>(x);
    k_mlp1<<<BB * 512 * 32 / 256, 256>>>(W1, b1);
    k_ln<<<BB, 512>>>(lng, lnb);
    k_mlp2<<<BB * 256 * 32 / 256, 256>>>(W2, b2);
    k_logits<<<BB * NIN * 32 / 256, 256>>>(nk);
    k_topk<<<BB, 1024>>>(p_logits, NIN, KI, p_iidx);

    // stage 1: sel_in = gelu(x @ gathered_patterns^T)
    k_gather_wsel<<<(int)((size_t)BB * NP * KI / 256), 256>>>(pw);
    sgemm_nt<true, true><<<dim3(KI / 128, SS / 128, BB), 256>>>(
        x, ip, p_selin, p_iidx, SS, KI, DM,
        (size_t)SS * DM, 0, (size_t)SS * KI, KI);

    // stage 2: pa = gelu(sel_in @ W_sel^T)
    sgemm_nt<true, false><<<dim3(NP / 128, SS / 128, BB), 256>>>(
        p_selin, p_wsel, p_pa, nullptr, SS, NP, KI,
        (size_t)SS * KI, (size_t)NP * KI, (size_t)SS * NP, 0);

    // process selection
    k_scores<<<BB * NP / 256, 256>>>();
    k_topk<<<BB, 1024>>>(p_scores, NP, KP, p_pidx);
    k_gather_pasel<<<(int)((size_t)BB * SS * KP / 256), 256>>>();

    // final: out = pa_sel @ gathered process_outputs
    sgemm_nn_g<<<dim3(DM / 128, SS / 128, BB), 256>>>(
        p_pasel, po, out, p_pidx, SS, DM, KP,
        (size_t)SS * KP, (size_t)SS * DM, KP);
}

// round 6
// speedup vs baseline: 1.5421x; 1.5421x over previous
#include <cuda_runtime.h>
#include <math.h>
#include <cstdint>

// Problem constants (fixed by dataset; k_input=2048, k_process=1024 always)
#define BB   8
#define SS   2048
#define DM   1024
#define NIN  4096
#define NP   2048
#define DR   256
#define KI   2048
#define KP   1024

// ---------------- scratch (static __device__ globals; no allocation) ----------------
__device__ float g_gctx [BB * DM];
__device__ float g_h    [BB * 512];
__device__ float g_hn   [BB * 512];
__device__ float g_query[BB * DR];
__device__ float g_logits[BB * NIN];
__device__ float g_scores[BB * NP];
__device__ int   g_iidx [BB * KI];
__device__ int   g_pidx [BB * KP];
__device__ float g_selin[(size_t)BB * SS * KI];   // 134 MB
__device__ float g_wsel [(size_t)BB * NP * KI];   // 134 MB
__device__ float g_pa   [(size_t)BB * SS * NP];   // 134 MB
__device__ float g_pasel[(size_t)BB * SS * KP];   //  67 MB
__device__ float g_poT  [(size_t)BB * DM * KP];   //  67 MB

__device__ __forceinline__ float geluf(float v) {
    return 0.5f * v * (1.0f + erff(v * 0.70710678118654752440f));
}

__device__ __forceinline__ uint32_t smem_u32(const void* p) {
    uint32_t a;
    asm("{ .reg .u64 t; cvta.to.shared.u64 t, %1; cvt.u32.u64 %0, t; }" : "=r"(a) : "l"(p));
    return a;
}

__device__ __forceinline__ void cp16(uint32_t dst, const void* src) {
    asm volatile("cp.async.cg.shared.global [%0], [%1], 16;" :: "r"(dst), "l"(src) : "memory");
}

__device__ __forceinline__ uint32_t tf32_hi(float x) {
    return __float_as_uint(x) & 0xFFFFE000u;
}
__device__ __forceinline__ uint32_t tf32_lo(float x, uint32_t h) {
    float l = x - __uint_as_float(h);
    return __float_as_uint(l) & 0xFFFFE000u;
}

__device__ __forceinline__ void mma8(float* c,
    uint32_t a0, uint32_t a1, uint32_t a2, uint32_t a3, uint32_t b0, uint32_t b1) {
    asm volatile(
        "mma.sync.aligned.m16n8k8.row.col.f32.tf32.tf32.f32 "
        "{%0,%1,%2,%3}, {%4,%5,%6,%7}, {%8,%9}, {%0,%1,%2,%3};"
        : "+f"(c[0]), "+f"(c[1]), "+f"(c[2]), "+f"(c[3])
        : "r"(a0), "r"(a1), "r"(a2), "r"(a3), "r"(b0), "r"(b1));
}

// smem: As[2][128*36] then Bs[2][128*36] floats (pad 36 => conflict-free frags)
#define STG_FLOATS (128 * 36)
#define SMEM_BYTES (4 * STG_FLOATS * 4)

// ---------------- 3xTF32 mma.sync GEMM: C = act(A * B^T) ----------------
// A [M x K] row-major K-contig, B [N x K] row-major K-contig (optional row gather).
// CTA tile 128x128, BK=32, 256 threads (8 warps, 4M x 2N), warp tile 32x64.
template<bool DOGELU, bool GATHERB>
__global__ void __launch_bounds__(256) mma_nt(
    const float* __restrict__ A, const float* __restrict__ Bm, float* __restrict__ Cm,
    const int* __restrict__ gidx, int Ncols, int K,
    size_t sA, size_t sB, size_t sC, int sG)
{
    extern __shared__ __align__(16) float smem[];
    const int tid = threadIdx.x, wid = tid >> 5, lane = tid & 31;
    const int lq = lane >> 2, lr = lane & 3;
    const int wm = wid & 3, wn = wid >> 2;
    const int zb = blockIdx.z;
    A  += (size_t)zb * sA;
    Bm += (size_t)zb * sB;
    Cm += (size_t)zb * sC;
    const int m0 = blockIdx.y * 128, n0 = blockIdx.x * 128;

    const uint32_t sbA = smem_u32(smem);
    const uint32_t sbB = sbA + 2 * STG_FLOATS * 4;

    // loader: 4 chunks of 16B each for A and B per thread per stage
    const float* aSrc[4]; const float* bSrc[4]; uint32_t dOff[4];
    #pragma unroll
    for (int c = 0; c < 4; c++) {
        int id = tid + 256 * c;
        int r = id >> 3, kc = (id & 7) * 4;
        aSrc[c] = A + (size_t)(m0 + r) * K + kc;
        int br = n0 + r;
        int bs_ = GATHERB ? gidx[(size_t)zb * sG + br] : br;
        bSrc[c] = Bm + (size_t)bs_ * K + kc;
        dOff[c] = (uint32_t)(r * 36 + kc) * 4;
    }

    float acc[2][8][4];
    #pragma unroll
    for (int mf = 0; mf < 2; mf++)
        #pragma unroll
        for (int nf = 0; nf < 8; nf++)
            #pragma unroll
            for (int q = 0; q < 4; q++) acc[mf][nf][q] = 0.f;

    const int T = K >> 5;

    // prologue: stage 0
    #pragma unroll
    for (int c = 0; c < 4; c++) {
        cp16(sbA + dOff[c], aSrc[c]);
        cp16(sbB + dOff[c], bSrc[c]);
    }
    asm volatile("cp.async.commit_group;" ::: "memory");

    for (int i = 0; i < T; i++) {
        asm volatile("cp.async.wait_group 0;" ::: "memory");
        __syncthreads();
        if (i + 1 < T) {
            uint32_t so = (uint32_t)(((i + 1) & 1) * STG_FLOATS) * 4;
            int kb = (i + 1) * 32;
            #pragma unroll
            for (int c = 0; c < 4; c++) {
                cp16(sbA + so + dOff[c], aSrc[c] + kb);
                cp16(sbB + so + dOff[c], bSrc[c] + kb);
            }
            asm volatile("cp.async.commit_group;" ::: "memory");
        }

        const float* Asf = smem + (i & 1) * STG_FLOATS + (wm * 32) * 36;
        const float* Bsf = smem + 2 * STG_FLOATS + (i & 1) * STG_FLOATS + (wn * 64) * 36;

        #pragma unroll
        for (int ks = 0; ks < 4; ks++) {
            const int c0 = ks * 8 + lr;
            // A fragments (fp32) then split
            uint32_t ah[2][4], al[2][4];
            #pragma unroll
            for (int mf = 0; mf < 2; mf++) {
                int rb = mf * 16 + lq;
                float a0 = Asf[rb * 36 + c0];
                float a1 = Asf[(rb + 8) * 36 + c0];
                float a2 = Asf[rb * 36 + c0 + 4];
                float a3 = Asf[(rb + 8) * 36 + c0 + 4];
                ah[mf][0] = tf32_hi(a0); al[mf][0] = tf32_lo(a0, ah[mf][0]);
                ah[mf][1] = tf32_hi(a1); al[mf][1] = tf32_lo(a1, ah[mf][1]);
                ah[mf][2] = tf32_hi(a2); al[mf][2] = tf32_lo(a2, ah[mf][2]);
                ah[mf][3] = tf32_hi(a3); al[mf][3] = tf32_lo(a3, ah[mf][3]);
            }
            // B fragments
            uint32_t bh[8][2], bl[8][2];
            #pragma unroll
            for (int nf = 0; nf < 8; nf++) {
                int nr = nf * 8 + lq;
                float b0 = Bsf[nr * 36 + c0];
                float b1 = Bsf[nr * 36 + c0 + 4];
                bh[nf][0] = tf32_hi(b0); bl[nf][0] = tf32_lo(b0, bh[nf][0]);
                bh[nf][1] = tf32_hi(b1); bl[nf][1] = tf32_lo(b1, bh[nf][1]);
            }
            #pragma unroll
            for (int mf = 0; mf < 2; mf++)
                #pragma unroll
                for (int nf = 0; nf < 8; nf++) {
                    mma8(acc[mf][nf], ah[mf][0], ah[mf][1], ah[mf][2], ah[mf][3], bh[nf][0], bh[nf][1]);
                    mma8(acc[mf][nf], al[mf][0], al[mf][1], al[mf][2], al[mf][3], bh[nf][0], bh[nf][1]);
                    mma8(acc[mf][nf], ah[mf][0], ah[mf][1], ah[mf][2], ah[mf][3], bl[nf][0], bl[nf][1]);
                }
        }
        __syncthreads();
    }

    // epilogue
    #pragma unroll
    for (int mf = 0; mf < 2; mf++) {
        int row0 = m0 + wm * 32 + mf * 16 + lq;
        #pragma unroll
        for (int nf = 0; nf < 8; nf++) {
            int col = n0 + wn * 64 + nf * 8 + 2 * lr;
            float2 v0, v1;
            v0.x = acc[mf][nf][0]; v0.y = acc[mf][nf][1];
            v1.x = acc[mf][nf][2]; v1.y = acc[mf][nf][3];
            if (DOGELU) {
                v0.x = geluf(v0.x); v0.y = geluf(v0.y);
                v1.x = geluf(v1.x); v1.y = geluf(v1.y);
            }
            *(float2*)(Cm + (size_t)row0 * Ncols + col) = v0;
            *(float2*)(Cm + (size_t)(row0 + 8) * Ncols + col) = v1;
        }
    }
}

// ---------------- router ----------------
__global__ void k_rowmax(const float* __restrict__ x) {
    int t = blockIdx.x * blockDim.x + threadIdx.x;
    int b = t >> 10, d = t & (DM - 1);
    const float* p = x + (size_t)b * SS * DM + d;
    float m = -INFINITY;
    #pragma unroll 8
    for (int s = 0; s < SS; s++) m = fmaxf(m, p[(size_t)s * DM]);
    g_gctx[t] = m;
}

__global__ void k_mlp1(const float* __restrict__ W1, const float* __restrict__ b1) {
    int gw = (blockIdx.x * blockDim.x + threadIdx.x) >> 5;
    int lane = threadIdx.x & 31;
    int b = gw >> 9, o = gw & 511;
    const float* g = g_gctx + b * DM;
    const float* w = W1 + (size_t)o * DM;
    float s = 0.f;
    for (int k = lane; k < DM; k += 32) s += g[k] * w[k];
    #pragma unroll
    for (int off = 16; off; off >>= 1) s += __shfl_xor_sync(0xffffffffu, s, off);
    if (lane == 0) g_h[gw] = geluf(s + b1[o]);
}

__global__ void k_ln(const float* __restrict__ lng, const float* __restrict__ lnb) {
    __shared__ float red[512];
    int b = blockIdx.x, tid = threadIdx.x;
    float v = g_h[b * 512 + tid];
    red[tid] = v;
    for (int s = 256; s; s >>= 1) { __syncthreads(); if (tid < s) red[tid] += red[tid + s]; }
    __syncthreads();
    float mu = red[0] * (1.f / 512.f);
    __syncthreads();
    float dv = v - mu;
    red[tid] = dv * dv;
    for (int s = 256; s; s >>= 1) { __syncthreads(); if (tid < s) red[tid] += red[tid + s]; }
    __syncthreads();
    float var = red[0] * (1.f / 512.f);
    g_hn[b * 512 + tid] = dv * rsqrtf(var + 1e-5f) * lng[tid] + lnb[tid];
}

__global__ void k_mlp2(const float* __restrict__ W2, const float* __restrict__ b2) {
    int gw = (blockIdx.x * blockDim.x + threadIdx.x) >> 5;
    int lane = threadIdx.x & 31;
    int b = gw >> 8, o = gw & 255;
    const float* hrow = g_hn + b * 512;
    const float* w = W2 + (size_t)o * 512;
    float s = 0.f;
    for (int k = lane; k < 512; k += 32) s += hrow[k] * w[k];
    #pragma unroll
    for (int off = 16; off; off >>= 1) s += __shfl_xor_sync(0xffffffffu, s, off);
    if (lane == 0) g_query[gw] = s + b2[o];
}

__global__ void k_logits(const float* __restrict__ nk) {
    int gw = (blockIdx.x * blockDim.x + threadIdx.x) >> 5;
    int lane = threadIdx.x & 31;
    int b = gw >> 12, n = gw & (NIN - 1);
    const float* q = g_query + b * DR;
    const float* w = nk + (size_t)n * DR;
    float s = 0.f;
    #pragma unroll
    for (int k = lane; k < DR; k += 32) s += q[k] * w[k];
    #pragma unroll
    for (int off = 16; off; off >>= 1) s += __shfl_xor_sync(0xffffffffu, s, off);
    if (lane == 0) g_logits[gw] = s * 0.0625f;
}

// ---------------- exact top-k via bitonic sort; index set emitted sorted ascending ----------------
__global__ void k_topk(const float* __restrict__ vals, int N, int Ksel, int* __restrict__ outIdx) {
    __shared__ float sv[4096];
    __shared__ int   si[4096];
    int b = blockIdx.x, tid = threadIdx.x, bs = blockDim.x;
    for (int i = tid; i < N; i += bs) { sv[i] = vals[b * N + i]; si[i] = i; }
    for (int k = 2; k <= N; k <<= 1) {
        for (int j = k >> 1; j > 0; j >>= 1) {
            __syncthreads();
            for (int i = tid; i < N; i += bs) {
                int l = i ^ j;
                if (l > i) {
                    float vi = sv[i], vl = sv[l];
                    int ii = si[i], il = si[l];
                    bool lFirst = (vl > vi) || (vl == vi && il < ii);
                    bool sw = ((i & k) == 0) ? lFirst : !lFirst;
                    if (sw) { sv[i] = vl; sv[l] = vi; si[i] = il; si[l] = ii; }
                }
            }
        }
    }
    __syncthreads();
    int* sel = (int*)sv;
    for (int i = tid; i < Ksel; i += bs) sel[i] = si[i];
    for (int k = 2; k <= Ksel; k <<= 1) {
        for (int j = k >> 1; j > 0; j >>= 1) {
            __syncthreads();
            for (int i = tid; i < Ksel; i += bs) {
                int l = i ^ j;
                if (l > i) {
                    int a = sel[i], c = sel[l];
                    bool sw = ((i & k) == 0) ? (c < a) : (c > a);
                    if (sw) { sel[i] = c; sel[l] = a; }
                }
            }
        }
    }
    __syncthreads();
    for (int i = tid; i < Ksel; i += bs) outIdx[b * Ksel + i] = sel[i];
}

// ---------------- gathers / reductions ----------------
__global__ void k_gather_wsel(const float* __restrict__ pw) {
    size_t t = (size_t)blockIdx.x * blockDim.x + threadIdx.x;
    int j = (int)(t & (KI - 1));
    size_t bp = t >> 11;
    int p = (int)(bp & (NP - 1));
    int b = (int)(bp >> 11);
    g_wsel[t] = pw[(size_t)p * NIN + g_iidx[b * KI + j]];
}

__global__ void k_scores() {
    int t = blockIdx.x * blockDim.x + threadIdx.x;
    int b = t >> 11, p = t & (NP - 1);
    const float* q = g_pa + (size_t)b * SS * NP + p;
    float s = 0.f;
    #pragma unroll 4
    for (int i = 0; i < SS; i++) s += q[(size_t)i * NP];
    g_scores[t] = s * (1.f / (float)SS);
}

__global__ void k_gather_pasel() {
    size_t t = (size_t)blockIdx.x * blockDim.x + threadIdx.x;
    int q = (int)(t & (KP - 1));
    size_t bs_ = t >> 10;
    int s = (int)(bs_ & (SS - 1));
    int b = (int)(bs_ >> 11);
    g_pasel[t] = g_pa[((size_t)(b * SS + s)) * NP + g_pidx[b * KP + q]];
}

// poT[b][d][q] = po[pidx[b][q]][d]   (32x32 smem transpose, coalesced both sides)
__global__ void k_build_poT(const float* __restrict__ po) {
    __shared__ float t[32][33];
    int b = blockIdx.z;
    int q0 = blockIdx.x * 32, d0 = blockIdx.y * 32;
    int tx = threadIdx.x, ty = threadIdx.y;
    for (int yy = ty; yy < 32; yy += 8) {
        int p = g_pidx[b * KP + q0 + yy];
        t[yy][tx] = po[(size_t)p * DM + d0 + tx];
    }
    __syncthreads();
    for (int yy = ty; yy < 32; yy += 8)
        g_poT[((size_t)b * DM + d0 + yy) * KP + q0 + tx] = t[tx][yy];
}

// ---------------- launch ----------------
extern "C" void kernel_launch(void* const* d_in, const int* in_sizes, int n_in,
                              void* d_out, int out_size) {
    const float* x   = (const float*)d_in[0];
    const float* W1  = (const float*)d_in[3];
    const float* b1  = (const float*)d_in[4];
    const float* lng = (const float*)d_in[5];
    const float* lnb = (const float*)d_in[6];
    const float* W2  = (const float*)d_in[7];
    const float* b2  = (const float*)d_in[8];
    const float* nk  = (const float*)d_in[9];
    const float* ip  = (const float*)d_in[10];
    const float* pw  = (const float*)d_in[11];
    const float* po  = (const float*)d_in[12];
    float* out = (float*)d_out;

    float *p_logits, *p_scores, *p_selin, *p_wsel, *p_pa, *p_pasel, *p_poT;
    int *p_iidx, *p_pidx;
    cudaGetSymbolAddress((void**)&p_logits, g_logits);
    cudaGetSymbolAddress((void**)&p_scores, g_scores);
    cudaGetSymbolAddress((void**)&p_selin,  g_selin);
    cudaGetSymbolAddress((void**)&p_wsel,   g_wsel);
    cudaGetSymbolAddress((void**)&p_pa,     g_pa);
    cudaGetSymbolAddress((void**)&p_pasel,  g_pasel);
    cudaGetSymbolAddress((void**)&p_poT,    g_poT);
    cudaGetSymbolAddress((void**)&p_iidx,   g_iidx);
    cudaGetSymbolAddress((void**)&p_pidx,   g_pidx);

    cudaFuncSetAttribute(mma_nt<true,  true >, cudaFuncAttributeMaxDynamicSharedMemorySize, SMEM_BYTES);
    cudaFuncSetAttribute(mma_nt<true,  false>, cudaFuncAttributeMaxDynamicSharedMemorySize, SMEM_BYTES);
    cudaFuncSetAttribute(mma_nt<false, false>, cudaFuncAttributeMaxDynamicSharedMemorySize, SMEM_BYTES);

    // router (fp32 exact)
    k_rowmax<<<BB * DM / 256, 256>>>(x);
    k_mlp1<<<BB * 512 * 32 / 256, 256>>>(W1, b1);
    k_ln<<<BB, 512>>>(lng, lnb);
    k_mlp2<<<BB * 256 * 32 / 256, 256>>>(W2, b2);
    k_logits<<<BB * NIN * 32 / 256, 256>>>(nk);
    k_topk<<<BB, 1024>>>(p_logits, NIN, KI, p_iidx);

    // stage 1: sel_in = gelu(x @ gathered_patterns^T)   [3xTF32 mma.sync]
    k_gather_wsel<<<(int)((size_t)BB * NP * KI / 256), 256>>>(pw);
    mma_nt<true, true><<<dim3(KI / 128, SS / 128, BB), 256, SMEM_BYTES>>>(
        x, ip, p_selin, p_iidx, KI, DM,
        (size_t)SS * DM, 0, (size_t)SS * KI, KI);

    // stage 2: pa = gelu(sel_in @ W_sel^T)   [3xTF32 mma.sync]
    mma_nt<true, false><<<dim3(NP / 128, SS / 128, BB), 256, SMEM_BYTES>>>(
        p_selin, p_wsel, p_pa, nullptr, NP, KI,
        (size_t)SS * KI, (size_t)NP * KI, (size_t)SS * NP, 0);

    // process selection
    k_scores<<<BB * NP / 256, 256>>>();
    k_topk<<<BB, 1024>>>(p_scores, NP, KP, p_pidx);
    k_gather_pasel<<<(int)((size_t)BB * SS * KP / 256), 256>>>();
    k_build_poT<<<dim3(KP / 32, DM / 32, BB), dim3(32, 8)>>>(po);

    // final: out = pa_sel @ poT^T   [3xTF32 mma.sync]
    mma_nt<false, false><<<dim3(DM / 128, SS / 128, BB), 256, SMEM_BYTES>>>(
        p_pasel, p_poT, out, nullptr, DM, KP,
        (size_t)SS * KP, (size_t)DM * KP, (size_t)SS * DM, 0);
}